// round 1
// baseline (speedup 1.0000x reference)
#include <cuda_runtime.h>

// ---------------------------------------------------------------------------
// SNN: 20 timesteps of  [Linear(1024->2048) + LIF]  ->  [Linear(2048->1024) + LIF]
// with s2 feedback into layer 1, then readout (spk_sum/20) @ Wo^T + bo.
// Round 1: exact fp32 fused SGEMM+LIF, multi-launch CUDA graph.
// ---------------------------------------------------------------------------

#define BATCH 4096
#define DIM_D 1024
#define DIM_H1 2048
#define DIM_H2 1024
#define DIM_C 64
#define NUM_STEPS 20

#define BETA 0.9f
#define THRV 1.0f

// Persistent state (device globals: allocation-free scratch).
__device__ float g_m1[(size_t)BATCH * DIM_H1];   // 32 MB
__device__ float g_m2[(size_t)BATCH * DIM_H2];   // 16 MB
__device__ float g_s1[(size_t)BATCH * DIM_H1];   // 32 MB
__device__ float g_s2[(size_t)BATCH * DIM_H2];   // 16 MB
__device__ float g_spk[(size_t)BATCH * DIM_H2];  // 16 MB

// ---------------------------------------------------------------------------
// Fused GEMM + LIF neuron update.
//   h[b,n]   = sum_k A[b,k] * W[n,k] + bias[n]        (A, W both K-major "NT")
//   r        = (m_old > THR) ? THR : 0
//   m_new    = BETA*m_old + h - r         (FIRST: m_old == 0)
//   s        = (m_new > THR) ? 1 : 0
//   mem      = m_new ; spk = s ; optionally spk_sum (+)= s
// Tiling: 128x128 CTA tile, BK=16, 256 threads, 8x8 per thread.
// ---------------------------------------------------------------------------
#define BM 128
#define BN 128
#define BK 16
#define TM 8
#define TN 8

template <bool FIRST, bool HAS_SPKSUM>
__global__ void __launch_bounds__(256, 2)
snn_gemm_lif(const float* __restrict__ A,     // [B, K]
             const float* __restrict__ W,     // [N, K]
             const float* __restrict__ bias,  // [N]
             float* __restrict__ mem,         // [B, N]
             float* __restrict__ spk,         // [B, N]
             float* __restrict__ spk_sum,     // [B, N] or unused
             int N, int K)
{
    __shared__ float As[BK][BM];
    __shared__ float Bs[BK][BN];

    const int tid = threadIdx.x;
    const int tx = tid & 15;        // 0..15  -> column group
    const int ty = tid >> 4;        // 0..15  -> row group

    const long brow = (long)blockIdx.y * BM;
    const long bcol = (long)blockIdx.x * BN;

    const float* Ab = A + brow * (long)K;
    const float* Wb = W + bcol * (long)K;

    float acc[TM][TN];
#pragma unroll
    for (int m = 0; m < TM; m++)
#pragma unroll
        for (int n = 0; n < TN; n++) acc[m][n] = 0.0f;

    for (int k0 = 0; k0 < K; k0 += BK) {
        // Cooperative load: 128 rows x 16 floats = 512 float4 per tile, 2 per thread.
#pragma unroll
        for (int i = 0; i < 2; i++) {
            int f = tid + i * 256;          // 0..511
            int r = f >> 2;                 // row in tile 0..127
            int kq = (f & 3) << 2;          // k offset 0,4,8,12
            float4 va = *reinterpret_cast<const float4*>(Ab + (long)r * K + k0 + kq);
            As[kq + 0][r] = va.x;
            As[kq + 1][r] = va.y;
            As[kq + 2][r] = va.z;
            As[kq + 3][r] = va.w;
            float4 vw = *reinterpret_cast<const float4*>(Wb + (long)r * K + k0 + kq);
            Bs[kq + 0][r] = vw.x;
            Bs[kq + 1][r] = vw.y;
            Bs[kq + 2][r] = vw.z;
            Bs[kq + 3][r] = vw.w;
        }
        __syncthreads();

#pragma unroll
        for (int k = 0; k < BK; k++) {
            float a[TM], bb[TN];
#pragma unroll
            for (int m = 0; m < TM; m++) a[m] = As[k][ty * TM + m];
#pragma unroll
            for (int n = 0; n < TN; n++) bb[n] = Bs[k][tx * TN + n];
#pragma unroll
            for (int m = 0; m < TM; m++)
#pragma unroll
                for (int n = 0; n < TN; n++) acc[m][n] = fmaf(a[m], bb[n], acc[m][n]);
        }
        __syncthreads();
    }

    // --- Fused LIF epilogue ---
    const long row0 = brow + ty * TM;
    const long col0 = bcol + tx * TN;

    float bfrag[TN];
#pragma unroll
    for (int n = 0; n < TN; n++) bfrag[n] = bias[col0 + n];

#pragma unroll
    for (int m = 0; m < TM; m++) {
        const long base = (row0 + m) * (long)N + col0;
#pragma unroll
        for (int n = 0; n < TN; n++) {
            float h = acc[m][n] + bfrag[n];
            float mn;
            if (FIRST) {
                mn = h;                              // mem was 0, no reset
            } else {
                float mo = mem[base + n];
                float r = (mo > THRV) ? THRV : 0.0f;
                mn = BETA * mo + h - r;
            }
            float s = (mn > THRV) ? 1.0f : 0.0f;
            mem[base + n] = mn;
            spk[base + n] = s;
            if (HAS_SPKSUM) {
                if (FIRST) spk_sum[base + n] = s;
                else       spk_sum[base + n] += s;
            }
        }
    }
}

// ---------------------------------------------------------------------------
// Readout: out[b,c] = (spk_sum[b,:]/NUM_STEPS) . Wo[c,:] + bo[c]
// 256 threads = 4 rows x 64 cols per block; K=1024 dot per thread.
// ---------------------------------------------------------------------------
__global__ void __launch_bounds__(256)
snn_readout(const float* __restrict__ spk_sum,  // [B, H2]
            const float* __restrict__ Wo,       // [C, H2]
            const float* __restrict__ bo,       // [C]
            float* __restrict__ out)            // [B, C]
{
    const int c  = threadIdx.x & 63;
    const int r4 = threadIdx.x >> 6;
    const long b = (long)blockIdx.x * 4 + r4;

    const float* s = spk_sum + b * DIM_H2;
    const float* w = Wo + (long)c * DIM_H2;

    float acc = 0.0f;
#pragma unroll 4
    for (int k = 0; k < DIM_H2; k += 4) {
        float4 sv = *reinterpret_cast<const float4*>(s + k);
        float4 wv = *reinterpret_cast<const float4*>(w + k);
        acc = fmaf(sv.x, wv.x, acc);
        acc = fmaf(sv.y, wv.y, acc);
        acc = fmaf(sv.z, wv.z, acc);
        acc = fmaf(sv.w, wv.w, acc);
    }
    out[b * DIM_C + c] = acc * (1.0f / (float)NUM_STEPS) + bo[c];
}

// ---------------------------------------------------------------------------
extern "C" void kernel_launch(void* const* d_in, const int* in_sizes, int n_in,
                              void* d_out, int out_size)
{
    const float* x  = (const float*)d_in[0];  // [4096, 1024]
    const float* W1 = (const float*)d_in[1];  // [2048, 1024]
    const float* b1 = (const float*)d_in[2];  // [2048]
    const float* W2 = (const float*)d_in[3];  // [1024, 2048]
    const float* b2 = (const float*)d_in[4];  // [1024]
    const float* Wo = (const float*)d_in[5];  // [64, 1024]
    const float* bo = (const float*)d_in[6];  // [64]
    // d_in[7] = num_steps (int scalar) == 20, fixed by problem setup.
    float* out = (float*)d_out;

    void *pm1, *pm2, *ps1, *ps2, *pspk;
    cudaGetSymbolAddress(&pm1, g_m1);
    cudaGetSymbolAddress(&pm2, g_m2);
    cudaGetSymbolAddress(&ps1, g_s1);
    cudaGetSymbolAddress(&ps2, g_s2);
    cudaGetSymbolAddress(&pspk, g_spk);
    float* m1  = (float*)pm1;
    float* m2  = (float*)pm2;
    float* s1  = (float*)ps1;
    float* s2  = (float*)ps2;
    float* spk = (float*)pspk;

    dim3 blk(256);
    dim3 g1(DIM_H1 / BN, BATCH / BM);  // 16 x 32
    dim3 g2(DIM_H2 / BN, BATCH / BM);  //  8 x 32

    // t = 0: mem starts at zero (FIRST variants avoid any state zero-init).
    snn_gemm_lif<true,  false><<<g1, blk>>>(x,  W1, b1, m1, s1, nullptr, DIM_H1, DIM_D);
    snn_gemm_lif<true,  true ><<<g2, blk>>>(s1, W2, b2, m2, s2, spk,     DIM_H2, DIM_H1);

    for (int t = 1; t < NUM_STEPS; t++) {
        snn_gemm_lif<false, false><<<g1, blk>>>(s2, W1, b1, m1, s1, nullptr, DIM_H1, DIM_D);
        snn_gemm_lif<false, true ><<<g2, blk>>>(s1, W2, b2, m2, s2, spk,     DIM_H2, DIM_H1);
    }

    snn_readout<<<BATCH / 4, blk>>>(spk, Wo, bo, out);
}

// round 3
// speedup vs baseline: 4.0873x; 4.0873x over previous
#include <cuda_runtime.h>
#include <cuda_fp16.h>
#include <cstdint>

// ===========================================================================
// SNN (20 steps, 2 fused Linear+LIF layers + feedback) on mma.sync (HMMA).
// Spikes stored as exactly 2^-11, weights split into 2 fp16 limbs scaled by
// 2^11 -> products are exact, residual ~|w|*2^-24 (fp32-equivalent).
// ===========================================================================

#define BATCH   4096
#define DIM_D   1024
#define DIM_H1  2048
#define DIM_H2  1024
#define DIM_C   64
#define NUM_STEPS 20
#define BETA 0.9f
#define THRV 1.0f

// ---------------------------------------------------------------------------
// Device-global state / scratch
// ---------------------------------------------------------------------------
__device__ float  g_m1 [(size_t)BATCH * DIM_H1];
__device__ float  g_m2 [(size_t)BATCH * DIM_H2];
__device__ float  g_spk[(size_t)BATCH * DIM_H2];
__device__ __half g_s1 [(size_t)BATCH * DIM_H1];
__device__ __half g_s2 [(size_t)BATCH * DIM_H2];
__device__ __half g_w1h [(size_t)DIM_H1 * DIM_D];   // W1 * 2^11, hi limb
__device__ __half g_w1l [(size_t)DIM_H1 * DIM_D];   // W1 * 2^11, lo limb
__device__ __half g_w1hu[(size_t)DIM_H1 * DIM_D];   // W1 hi limb, unscaled (t=0)
__device__ __half g_w2h [(size_t)DIM_H2 * DIM_H1];
__device__ __half g_w2l [(size_t)DIM_H2 * DIM_H1];
__device__ __half g_xh  [(size_t)BATCH * DIM_D];    // fp16(x)
__device__ __half g_xl  [(size_t)BATCH * DIM_D];    // fp16(x - xh)
__device__ __half g_xhs [(size_t)BATCH * DIM_D];    // fp16(xh * 2^-11)

// ---------------------------------------------------------------------------
// PTX helpers (sm_80-era: cp.async / ldmatrix / mma.sync -> works on sm_100)
// ---------------------------------------------------------------------------
__device__ __forceinline__ uint32_t smem_u32(const void* p) {
    uint32_t a;
    asm("{ .reg .u64 t; cvta.to.shared.u64 t, %1; cvt.u32.u64 %0, t; }"
        : "=r"(a) : "l"(p));
    return a;
}
__device__ __forceinline__ void cp16(uint32_t dst, const void* src) {
    asm volatile("cp.async.cg.shared.global [%0], [%1], 16;"
                 :: "r"(dst), "l"(__cvta_generic_to_global(src)) : "memory");
}
__device__ __forceinline__ void ldsm4(uint32_t addr, uint32_t& r0, uint32_t& r1,
                                      uint32_t& r2, uint32_t& r3) {
    asm volatile("ldmatrix.sync.aligned.m8n8.x4.shared.b16 {%0,%1,%2,%3}, [%4];"
                 : "=r"(r0), "=r"(r1), "=r"(r2), "=r"(r3) : "r"(addr));
}
__device__ __forceinline__ void mma16816(float* c, const uint32_t a[4],
                                         uint32_t b0, uint32_t b1) {
    asm volatile(
        "mma.sync.aligned.m16n8k16.row.col.f32.f16.f16.f32 "
        "{%0,%1,%2,%3}, {%4,%5,%6,%7}, {%8,%9}, {%0,%1,%2,%3};"
        : "+f"(c[0]), "+f"(c[1]), "+f"(c[2]), "+f"(c[3])
        : "r"(a[0]), "r"(a[1]), "r"(a[2]), "r"(a[3]), "r"(b0), "r"(b1));
}

// ---------------------------------------------------------------------------
// Fused GEMM + LIF.  D[row,col] = sum_k A[row,k] * W[col,k]  (+ limb products)
// TZ=false: A=spikes(2^-11), products (A,W0)+(A,W1), W limbs scaled 2^11.
// TZ=true : A limbs {xh, xh*2^-11, xl}, products (0,W0),(1,W1),(2,W0),
//           W0 = unscaled hi limb, W1 = lo limb * 2^11.
// ---------------------------------------------------------------------------
template <bool TZ, bool FIRST, bool SUM>
__global__ void __launch_bounds__(256, 2)
snn_hmma(const __half* __restrict__ A0, const __half* __restrict__ A1,
         const __half* __restrict__ A2,
         const __half* __restrict__ W0, const __half* __restrict__ W1,
         const float* __restrict__ bias, float* __restrict__ mem,
         __half* __restrict__ spk, float* __restrict__ spk_sum,
         int N, int K)
{
    constexpr int NA = TZ ? 3 : 1;
    constexpr int TILE = 16384;                 // 128 rows x 128 bytes
    constexpr int STAGE = (NA + 2) * TILE;
    extern __shared__ char smem[];
    const uint32_t sb = smem_u32(smem);

    const int tid = threadIdx.x, lane = tid & 31, wid = tid >> 5;
    const int wm = wid >> 2, wn = wid & 3;
    const int brow = blockIdx.y * 128, bcol = blockIdx.x * 128;

    const __half* Ap[3];
    Ap[0] = A0 + (size_t)brow * K;
    Ap[1] = TZ ? A1 + (size_t)brow * K : Ap[0];
    Ap[2] = TZ ? A2 + (size_t)brow * K : Ap[0];
    const __half* Wp[2] = { W0 + (size_t)bcol * K, W1 + (size_t)bcol * K };

    auto load_stage = [&](int st, int k0) {
        const uint32_t s0 = sb + st * STAGE;
#pragma unroll
        for (int l = 0; l < NA; l++) {
            const __half* g = Ap[l];
            const uint32_t d = s0 + l * TILE;
            for (int q = tid; q < 1024; q += 256) {
                int r = q >> 3, c = q & 7;
                cp16(d + r * 128 + ((c ^ (r & 7)) << 4),
                     g + (size_t)r * K + k0 + c * 8);
            }
        }
#pragma unroll
        for (int l = 0; l < 2; l++) {
            const __half* g = Wp[l];
            const uint32_t d = s0 + (NA + l) * TILE;
            for (int q = tid; q < 1024; q += 256) {
                int r = q >> 3, c = q & 7;
                cp16(d + r * 128 + ((c ^ (r & 7)) << 4),
                     g + (size_t)r * K + k0 + c * 8);
            }
        }
        asm volatile("cp.async.commit_group;" ::: "memory");
    };

    // ldmatrix lane geometry
    const int arow = (lane & 7) + 8 * ((lane >> 3) & 1);   // A: m within 16
    const int asel = lane >> 4;                            // A: k-chunk select
    const int brw  = (lane & 7) + 8 * (lane >> 4);         // B: n within 16
    const int bsel = (lane >> 3) & 1;                      // B: k-chunk select
    const int sx   = lane & 7;                             // swizzle key

    float acc[4][4][4];
#pragma unroll
    for (int i = 0; i < 4; i++)
#pragma unroll
        for (int j = 0; j < 4; j++)
#pragma unroll
            for (int k = 0; k < 4; k++) acc[i][j][k] = 0.0f;

    const int nch = K / 64;
    load_stage(0, 0);

    for (int ch = 0; ch < nch; ch++) {
        if (ch + 1 < nch) {
            load_stage((ch + 1) & 1, (ch + 1) * 64);
            asm volatile("cp.async.wait_group 1;" ::: "memory");
        } else {
            asm volatile("cp.async.wait_group 0;" ::: "memory");
        }
        __syncthreads();

        const uint32_t s0 = sb + (ch & 1) * STAGE;
        uint32_t bb[2][2];
#pragma unroll
        for (int w = 0; w < 2; w++)
#pragma unroll
            for (int h = 0; h < 2; h++)
                bb[w][h] = s0 + (NA + w) * TILE + (wn * 32 + h * 16 + brw) * 128;

#pragma unroll
        for (int ks = 0; ks < 4; ks++) {
            uint32_t b[2][8];
#pragma unroll
            for (int w = 0; w < 2; w++) {
                const uint32_t off = ((2 * ks + bsel) ^ sx) << 4;
                ldsm4(bb[w][0] + off, b[w][0], b[w][1], b[w][2], b[w][3]);
                ldsm4(bb[w][1] + off, b[w][4], b[w][5], b[w][6], b[w][7]);
            }
            const uint32_t aoff = ((2 * ks + asel) ^ sx) << 4;
            if (!TZ) {
                uint32_t a[4][4];
#pragma unroll
                for (int mf = 0; mf < 4; mf++)
                    ldsm4(s0 + (wm * 64 + mf * 16 + arow) * 128 + aoff,
                          a[mf][0], a[mf][1], a[mf][2], a[mf][3]);
#pragma unroll
                for (int w = 0; w < 2; w++)
#pragma unroll
                    for (int mf = 0; mf < 4; mf++)
#pragma unroll
                        for (int nf = 0; nf < 4; nf++)
                            mma16816(acc[mf][nf], a[mf], b[w][2 * nf], b[w][2 * nf + 1]);
            } else {
                const int PA[3] = {0, 1, 2}, PW[3] = {0, 1, 0};
#pragma unroll
                for (int p = 0; p < 3; p++) {
                    uint32_t a[4][4];
#pragma unroll
                    for (int mf = 0; mf < 4; mf++)
                        ldsm4(s0 + PA[p] * TILE + (wm * 64 + mf * 16 + arow) * 128 + aoff,
                              a[mf][0], a[mf][1], a[mf][2], a[mf][3]);
#pragma unroll
                    for (int mf = 0; mf < 4; mf++)
#pragma unroll
                        for (int nf = 0; nf < 4; nf++)
                            mma16816(acc[mf][nf], a[mf], b[PW[p]][2 * nf], b[PW[p]][2 * nf + 1]);
                }
            }
        }
        __syncthreads();
    }

    // ---- Fused LIF epilogue on register accumulators ----
    const int qr = lane >> 2, qc = (lane & 3) * 2;
#pragma unroll
    for (int mf = 0; mf < 4; mf++)
#pragma unroll
    for (int h = 0; h < 2; h++) {
        const int row = brow + wm * 64 + mf * 16 + qr + 8 * h;
#pragma unroll
        for (int nf = 0; nf < 4; nf++) {
            const int col = bcol + wn * 32 + nf * 8 + qc;
            const size_t ix = (size_t)row * N + col;
            float v0 = acc[mf][nf][2 * h + 0] + bias[col];
            float v1 = acc[mf][nf][2 * h + 1] + bias[col + 1];
            float m0, m1v;
            if (FIRST) {
                m0 = v0; m1v = v1;
            } else {
                float2 mo = *reinterpret_cast<const float2*>(mem + ix);
                m0  = BETA * mo.x + v0 - ((mo.x > THRV) ? THRV : 0.0f);
                m1v = BETA * mo.y + v1 - ((mo.y > THRV) ? THRV : 0.0f);
            }
            const bool sp0 = m0 > THRV, sp1 = m1v > THRV;
            *reinterpret_cast<float2*>(mem + ix) = make_float2(m0, m1v);
            // spike value = 2^-11 exactly (fp16 bits 0x1000)
            uint32_t sv = (sp0 ? 0x1000u : 0u) | (sp1 ? 0x10000000u : 0u);
            *reinterpret_cast<uint32_t*>(spk + ix) = sv;
            if (SUM) {
                float a0 = sp0 ? 1.0f : 0.0f, a1 = sp1 ? 1.0f : 0.0f;
                float2* ss = reinterpret_cast<float2*>(spk_sum + ix);
                if (FIRST) {
                    *ss = make_float2(a0, a1);
                } else {
                    float2 o = *ss;
                    *ss = make_float2(o.x + a0, o.y + a1);
                }
            }
        }
    }
}

// ---------------------------------------------------------------------------
// Weight split: hS = fp16(w*2048), lS = fp16(w*2048 - hS), hU = hS * 2^-11.
// ---------------------------------------------------------------------------
__global__ void __launch_bounds__(256)
split_w(const float* __restrict__ w, __half* __restrict__ hS,
        __half* __restrict__ lS, __half* __restrict__ hU, int n, int mkU)
{
    for (int i = blockIdx.x * 256 + threadIdx.x; i < n; i += gridDim.x * 256) {
        float v = w[i] * 2048.0f;
        __half h = __float2half_rn(v);
        float r = v - __half2float(h);
        hS[i] = h;
        lS[i] = __float2half_rn(r);
        if (mkU) hU[i] = __float2half_rn(__half2float(h) * (1.0f / 2048.0f));
    }
}

// x split: xh = fp16(x), xl = fp16(x - xh), xhs = fp16(xh * 2^-11)
__global__ void __launch_bounds__(256)
split_x(const float* __restrict__ x, __half* __restrict__ xh,
        __half* __restrict__ xl, __half* __restrict__ xhs, int n)
{
    for (int i = blockIdx.x * 256 + threadIdx.x; i < n; i += gridDim.x * 256) {
        float v = x[i];
        __half h = __float2half_rn(v);
        float r = v - __half2float(h);
        xh[i] = h;
        xl[i] = __float2half_rn(r);
        xhs[i] = __float2half_rn(__half2float(h) * (1.0f / 2048.0f));
    }
}

// ---------------------------------------------------------------------------
// Readout: out[b,c] = (spk_sum[b,:]/NUM_STEPS) . Wo[c,:] + bo[c]
// ---------------------------------------------------------------------------
__global__ void __launch_bounds__(256)
snn_readout(const float* __restrict__ spk_sum, const float* __restrict__ Wo,
            const float* __restrict__ bo, float* __restrict__ out)
{
    const int c  = threadIdx.x & 63;
    const int r4 = threadIdx.x >> 6;
    const size_t b = (size_t)blockIdx.x * 4 + r4;
    const float* s = spk_sum + b * DIM_H2;
    const float* w = Wo + (size_t)c * DIM_H2;
    float acc = 0.0f;
#pragma unroll 4
    for (int k = 0; k < DIM_H2; k += 4) {
        float4 sv = *reinterpret_cast<const float4*>(s + k);
        float4 wv = *reinterpret_cast<const float4*>(w + k);
        acc = fmaf(sv.x, wv.x, acc);
        acc = fmaf(sv.y, wv.y, acc);
        acc = fmaf(sv.z, wv.z, acc);
        acc = fmaf(sv.w, wv.w, acc);
    }
    out[b * DIM_C + c] = acc * (1.0f / (float)NUM_STEPS) + bo[c];
}

// ---------------------------------------------------------------------------
extern "C" void kernel_launch(void* const* d_in, const int* in_sizes, int n_in,
                              void* d_out, int out_size)
{
    const float* x  = (const float*)d_in[0];
    const float* W1 = (const float*)d_in[1];
    const float* b1 = (const float*)d_in[2];
    const float* W2 = (const float*)d_in[3];
    const float* b2 = (const float*)d_in[4];
    const float* Wo = (const float*)d_in[5];
    const float* bo = (const float*)d_in[6];
    float* out = (float*)d_out;

    auto sym = [](const void* s) { void* p; cudaGetSymbolAddress(&p, s); return p; };
    float*  m1   = (float*)sym(g_m1);
    float*  m2   = (float*)sym(g_m2);
    float*  spk  = (float*)sym(g_spk);
    __half* s1   = (__half*)sym(g_s1);
    __half* s2   = (__half*)sym(g_s2);
    __half* w1h  = (__half*)sym(g_w1h);
    __half* w1l  = (__half*)sym(g_w1l);
    __half* w1hu = (__half*)sym(g_w1hu);
    __half* w2h  = (__half*)sym(g_w2h);
    __half* w2l  = (__half*)sym(g_w2l);
    __half* xh   = (__half*)sym(g_xh);
    __half* xl   = (__half*)sym(g_xl);
    __half* xhs  = (__half*)sym(g_xhs);

    constexpr int SM_STD = 2 * 3 * 16384;   //  98304 B
    constexpr int SM_TZ  = 2 * 5 * 16384;   // 163840 B
    cudaFuncSetAttribute(snn_hmma<true,  true,  false>, cudaFuncAttributeMaxDynamicSharedMemorySize, SM_TZ);
    cudaFuncSetAttribute(snn_hmma<false, true,  true >, cudaFuncAttributeMaxDynamicSharedMemorySize, SM_STD);
    cudaFuncSetAttribute(snn_hmma<false, false, false>, cudaFuncAttributeMaxDynamicSharedMemorySize, SM_STD);
    cudaFuncSetAttribute(snn_hmma<false, false, true >, cudaFuncAttributeMaxDynamicSharedMemorySize, SM_STD);

    split_w<<<2048, 256>>>(W1, w1h, w1l, w1hu, DIM_H1 * DIM_D, 1);
    split_w<<<2048, 256>>>(W2, w2h, w2l, nullptr, DIM_H2 * DIM_H1, 0);
    split_x<<<2048, 256>>>(x, xh, xl, xhs, BATCH * DIM_D);

    dim3 blk(256);
    dim3 g1(DIM_H1 / 128, BATCH / 128);   // (16, 32)
    dim3 g2(DIM_H2 / 128, BATCH / 128);   // (8, 32)

    // t = 0 (mem starts at zero)
    snn_hmma<true, true, false><<<g1, blk, SM_TZ>>>(
        xh, xhs, xl, w1hu, w1l, b1, m1, s1, nullptr, DIM_H1, DIM_D);
    snn_hmma<false, true, true><<<g2, blk, SM_STD>>>(
        s1, nullptr, nullptr, w2h, w2l, b2, m2, s2, spk, DIM_H2, DIM_H1);

    for (int t = 1; t < NUM_STEPS; t++) {
        snn_hmma<false, false, false><<<g1, blk, SM_STD>>>(
            s2, nullptr, nullptr, w1h, w1l, b1, m1, s1, nullptr, DIM_H1, DIM_D);
        snn_hmma<false, false, true><<<g2, blk, SM_STD>>>(
            s1, nullptr, nullptr, w2h, w2l, b2, m2, s2, spk, DIM_H2, DIM_H1);
    }

    snn_readout<<<BATCH / 4, blk>>>(spk, Wo, bo, out);
}